// round 14
// baseline (speedup 1.0000x reference)
#include <cuda_runtime.h>
#include <cuda_fp16.h>
#include <cstdint>

#define NPIX  12544
#define CIN   64
#define COUT  128
#define KTOT  576
#define IMG_W 112
#define BB    16
#define NTILE 64            // pixels per CTA
#define KCH   32            // one chunk = 32 channels of ONE kernel tap
#define NCH   18            // 576/32
#define ROWB  64            // bytes per smem row (32 halves)

// ---- device globals ----
__device__ __half g_spw2[NCH * COUT * KCH];   // weights, chunk-major, tap-major K, swizzle baked

__global__ void spw2_kernel(const float* __restrict__ w, const float* __restrict__ m) {
    int i = blockIdx.x * blockDim.x + threadIdx.x;
    if (i < NCH * COUT * KCH) {
        int t   = i / (COUT * KCH);
        int rem = i - t * (COUT * KCH);
        int r   = rem / KCH;
        int s   = rem - r * KCH;
        int blk = s >> 3;
        int within = s & 7;
        int oblk = blk ^ ((r >> 1) & 3);          // undo read-side swizzle
        int kic  = oblk * 8 + within;
        int rm   = t >> 1;                        // tap 0..8
        int ci   = (t & 1) * 32 + kic;            // channel 0..63
        int k    = ci * 9 + rm;
        g_spw2[i] = __float2half_rn(w[r * KTOT + k] * m[r * KTOT + k]);
    }
}

// ---- asm helpers ----
__device__ __forceinline__ uint32_t smem_u32(const void* p) {
    uint32_t a;
    asm("{ .reg .u64 t; cvta.to.shared.u64 t, %1; cvt.u32.u64 %0, t; }" : "=r"(a) : "l"(p));
    return a;
}
__device__ __forceinline__ void cpasync16(uint32_t dst, const void* src) {
    asm volatile("cp.async.cg.shared.global [%0], [%1], 16;" :: "r"(dst), "l"(src));
}
__device__ __forceinline__ void ldsm_x4(uint32_t& r0, uint32_t& r1, uint32_t& r2,
                                        uint32_t& r3, uint32_t addr) {
    asm volatile("ldmatrix.sync.aligned.m8n8.x4.shared.b16 {%0,%1,%2,%3}, [%4];"
                 : "=r"(r0), "=r"(r1), "=r"(r2), "=r"(r3) : "r"(addr));
}
__device__ __forceinline__ void mma16816(float* c, uint32_t a0, uint32_t a1,
                                         uint32_t a2, uint32_t a3,
                                         uint32_t b0, uint32_t b1) {
    asm volatile(
        "mma.sync.aligned.m16n8k16.row.col.f32.f16.f16.f32 "
        "{%0,%1,%2,%3},{%4,%5,%6,%7},{%8,%9},{%0,%1,%2,%3};"
        : "+f"(c[0]), "+f"(c[1]), "+f"(c[2]), "+f"(c[3])
        : "r"(a0), "r"(a1), "r"(a2), "r"(a3), "r"(b0), "r"(b1));
}

// ---- main kernel ----
__global__ __launch_bounds__(256, 3)
void conv_mma(const float* __restrict__ x, const float* __restrict__ bias,
              float* __restrict__ out) {
    __shared__ __align__(16) __half As[2][COUT * KCH];    // 2 x 8192B
    __shared__ __align__(16) __half Bs[2][NTILE * KCH];   // 2 x 4096B  (total 24KB)

    const int tid  = threadIdx.x;
    const int lane = tid & 31;
    const int wid  = tid >> 5;           // 0..7
    const int wm   = wid & 3;            // 32-cout tile
    const int wn   = wid >> 2;           // 32-pixel tile (0..1)

    const uint32_t sA[2] = { smem_u32(&As[0][0]), smem_u32(&As[1][0]) };
    const uint32_t sB[2] = { smem_u32(&Bs[0][0]), smem_u32(&Bs[1][0]) };

    // ldmatrix per-lane geometry
    const int a_row = wm * 32 + ((lane >> 3) & 1) * 8 + (lane & 7);
    const int a_cb  = lane >> 4;
    const int a_swz = (a_row >> 1) & 3;
    const int b_row = wn * 32 + ((lane >> 4)) * 8 + (lane & 7);
    const int b_cb  = (lane >> 3) & 1;
    const int b_swz = (b_row >> 1) & 3;

    // geometry: 196 tiles of 64 pixels per image
    const int bi = blockIdx.x;
    const int b  = bi / 196;
    const int m0 = (bi - b * 196) * NTILE;
    const float* xb = x + (size_t)b * CIN * NPIX;

    // fill roles: p = pixel (0..63), kq = channel-eighth (8 channels)
    const int p  = tid & 63;
    const int kq = tid >> 6;             // 0..3
    const int gpix = m0 + p;
    const int ph = gpix / IMG_W;
    const int pw = gpix - ph * IMG_W;
    unsigned vm = 0;
    #pragma unroll
    for (int rr = 0; rr < 3; ++rr)
        #pragma unroll
        for (int jj = 0; jj < 3; ++jj)
            if ((unsigned)(ph + rr - 1) < (unsigned)IMG_W &&
                (unsigned)(pw + jj - 1) < (unsigned)IMG_W)
                vm |= 1u << (rr * 3 + jj);
    const int bswz = (p >> 1) & 3;
    const float* xpix = xb + gpix;

    float c[2][4][4];
    #pragma unroll
    for (int mt = 0; mt < 2; ++mt)
        #pragma unroll
        for (int nt = 0; nt < 4; ++nt)
            #pragma unroll
            for (int i = 0; i < 4; ++i) c[mt][nt][i] = 0.f;

    // B-fill: chunk t = tap rm (t>>1), channels (t&1)*32 + kq*8 + [0,8)
    auto b_fill = [&](int t, int buf) {
        const int rm = t >> 1;
        const int dr = rm / 3;
        const int dc = rm - dr * 3;
        const bool valid = (vm >> rm) & 1u;
        const float* bp = xpix + (dr - 1) * IMG_W + (dc - 1)
                        + ((t & 1) * 32 + kq * 8) * NPIX;
        float v[8];
        if (valid) {
            #pragma unroll
            for (int j = 0; j < 8; ++j) v[j] = __ldg(bp + (size_t)j * NPIX);
        } else {
            #pragma unroll
            for (int j = 0; j < 8; ++j) v[j] = 0.f;
        }
        uint32_t bpack[4];
        #pragma unroll
        for (int j = 0; j < 4; ++j) {
            __half2 hh = __floats2half2_rn(v[2 * j], v[2 * j + 1]);
            bpack[j] = *(uint32_t*)&hh;
        }
        char* rowp = (char*)&Bs[buf][0] + p * ROWB;
        *(uint4*)(rowp + ((kq ^ bswz) * 16)) =
            make_uint4(bpack[0], bpack[1], bpack[2], bpack[3]);
    };
    auto a_fill = [&](int t, int buf) {
        const __half* asrc = g_spw2 + (size_t)t * (COUT * KCH) + tid * 16;
        uint32_t adst = sA[buf] + tid * 32;
        cpasync16(adst, asrc);
        cpasync16(adst + 16, asrc + 8);
        asm volatile("cp.async.commit_group;" ::: "memory");
    };

    // ---- prologue: fill buf 0 ----
    a_fill(0, 0);
    b_fill(0, 0);
    asm volatile("cp.async.wait_group 0;" ::: "memory");
    __syncthreads();

    // ---- mainloop ----
    for (int t = 0; t < NCH; ++t) {
        const int cur = t & 1;
        const int nxt = cur ^ 1;
        const bool hasNext = (t + 1) < NCH;

        if (hasNext) {
            a_fill(t + 1, nxt);
            b_fill(t + 1, nxt);
        }

        // mma: 2 k-steps of 16
        #pragma unroll
        for (int ks = 0; ks < 2; ++ks) {
            uint32_t a[2][4];
            #pragma unroll
            for (int mt = 0; mt < 2; ++mt)
                ldsm_x4(a[mt][0], a[mt][1], a[mt][2], a[mt][3],
                        sA[cur] + (a_row + mt * 16) * ROWB + (((ks * 2 + a_cb) ^ a_swz) * 16));
            #pragma unroll
            for (int ntp = 0; ntp < 2; ++ntp) {
                uint32_t b0, b1, b2, b3;
                ldsm_x4(b0, b1, b2, b3,
                        sB[cur] + (b_row + ntp * 16) * ROWB + (((ks * 2 + b_cb) ^ b_swz) * 16));
                #pragma unroll
                for (int mt = 0; mt < 2; ++mt) {
                    mma16816(c[mt][2 * ntp],     a[mt][0], a[mt][1], a[mt][2], a[mt][3], b0, b1);
                    mma16816(c[mt][2 * ntp + 1], a[mt][0], a[mt][1], a[mt][2], a[mt][3], b2, b3);
                }
            }
        }

        asm volatile("cp.async.wait_group 0;" ::: "memory");
        __syncthreads();
    }

    // ---- epilogue ----
    const int g   = lane >> 2;
    const int tig = lane & 3;
    #pragma unroll
    for (int mt = 0; mt < 2; ++mt) {
        const int r0 = wm * 32 + mt * 16 + g;
        const float bv0 = __ldg(bias + r0);
        const float bv1 = __ldg(bias + r0 + 8);
        float* o0 = out + ((size_t)(b * COUT + r0)) * NPIX + m0;
        float* o1 = out + ((size_t)(b * COUT + r0 + 8)) * NPIX + m0;
        #pragma unroll
        for (int nt = 0; nt < 4; ++nt) {
            const int col = wn * 32 + nt * 8 + tig * 2;
            float2 v0 = { c[mt][nt][0] + bv0, c[mt][nt][1] + bv0 };
            float2 v1 = { c[mt][nt][2] + bv1, c[mt][nt][3] + bv1 };
            *(float2*)(o0 + col) = v0;
            *(float2*)(o1 + col) = v1;
        }
    }
}

extern "C" void kernel_launch(void* const* d_in, const int* in_sizes, int n_in,
                              void* d_out, int out_size) {
    const float* x      = (const float*)d_in[0];
    const float* weight = (const float*)d_in[1];
    const float* mask   = (const float*)d_in[2];
    const float* bias   = (const float*)d_in[3];
    float* out = (float*)d_out;

    spw2_kernel<<<(NCH * COUT * KCH + 255) / 256, 256>>>(weight, mask);
    conv_mma<<<BB * (NPIX / NTILE), 256>>>(x, bias, out);
}